// round 1
// baseline (speedup 1.0000x reference)
#include <cuda_runtime.h>

#define NB      32
#define NIN     1034
#define NOUT    512
#define STRIDE  1088          // NIN padded (need reads up to k0+32 and k+1)
#define KNS     1000.0f
#define MINW    (-0.3678794411714423f)
#define EF      2.718281828459045f

// scratch: sorted times, exp(t), t*exp(t), original index  (per batch row)
__device__ float g_ts [NB * STRIDE];
__device__ float g_z  [NB * STRIDE];
__device__ float g_zt [NB * STRIDE];
__device__ int   g_ord[NB * STRIDE];

// ---------------------------------------------------------------------------
// Kernel 1: per-batch bitonic sort of (time, idx) + precompute z, z*t
// ---------------------------------------------------------------------------
__global__ void sort_kernel(const float* __restrict__ x,
                            const float* __restrict__ pulse) {
    __shared__ unsigned long long s[2048];
    const int b   = blockIdx.x;
    const int tid = threadIdx.x;            // 1024 threads

    for (int i = tid; i < 2048; i += 1024) {
        float t;
        if (i < 1024)      t = x[b * 1024 + i];
        else if (i < NIN)  t = pulse[i - 1024];
        else               t = 3.0e38f;     // pad key (sorts to the end)
        // times are >= 0 so raw float bits are order-preserving as uint
        unsigned ub = __float_as_uint(t);
        s[i] = ((unsigned long long)ub << 32) | (unsigned)i;
    }
    __syncthreads();

    for (int k = 2; k <= 2048; k <<= 1) {
        for (int j = k >> 1; j > 0; j >>= 1) {
            for (int i = tid; i < 2048; i += 1024) {
                int ixj = i ^ j;
                if (ixj > i) {
                    unsigned long long a = s[i], c = s[ixj];
                    bool up = ((i & k) == 0);
                    if ((a > c) == up) { s[i] = c; s[ixj] = a; }
                }
            }
            __syncthreads();
        }
    }

    for (int i = tid; i < STRIDE; i += 1024) {
        int gi = b * STRIDE + i;
        if (i < NIN) {
            unsigned long long v = s[i];
            float t = __uint_as_float((unsigned)(v >> 32));
            int idx = (int)(unsigned)v;
            float z = expf(t);
            g_ts [gi] = t;
            g_z  [gi] = z;
            g_zt [gi] = z * t;
            g_ord[gi] = idx;
        } else {
            g_ts [gi] = KNS;   // sentinel: next_t for last element, invalid lanes
            g_z  [gi] = 0.0f;
            g_zt [gi] = 0.0f;
            g_ord[gi] = 0;
        }
    }
}

// ---------------------------------------------------------------------------
// Kernel 2: one warp per (batch, out-neuron). Chunked causal-set scan with
// warp-scan cumsum, Lambert-W threshold solve, first-valid early exit.
// ---------------------------------------------------------------------------
__global__ void solve_kernel(const float* __restrict__ W,
                             float* __restrict__ out) {
    const int gw   = (int)((blockIdx.x * blockDim.x + threadIdx.x) >> 5);
    const int lane = threadIdx.x & 31;
    const int b    = gw >> 9;        // /512
    const int o    = gw & 511;
    if (b >= NB) return;

    const float* __restrict__ ts  = g_ts  + b * STRIDE;
    const float* __restrict__ zz  = g_z   + b * STRIDE;
    const float* __restrict__ zts = g_zt  + b * STRIDE;
    const int*   __restrict__ ord = g_ord + b * STRIDE;
    const float* __restrict__ wrow = W + o * NIN;

    float carryA = 0.0f, carryB = 0.0f;
    float result = KNS;
    bool  done = false;

    for (int k0 = 0; k0 < NIN && !done; k0 += 32) {
        const int k = k0 + lane;
        const float t   = ts[k];
        const float z   = zz[k];
        const float zt_ = zts[k];
        const float w   = wrow[ord[k]];   // pad lanes: z=0 -> contribution 0

        float a  = w * z;
        float bb = w * zt_;
        // inclusive warp scan (Hillis-Steele)
        #pragma unroll
        for (int off = 1; off < 32; off <<= 1) {
            float ua = __shfl_up_sync(0xffffffffu, a,  off);
            float ub = __shfl_up_sync(0xffffffffu, bb, off);
            if (lane >= off) { a += ua; bb += ub; }
        }
        const float A = carryA + a;
        const float B = carryB + bb;
        const float totA = __shfl_sync(0xffffffffu, a,  31);
        const float totB = __shfl_sync(0xffffffffu, bb, 31);

        const bool  Apos  = A > 1e-10f;
        const float Asafe = Apos ? A : 1.0f;
        const float boa   = B / Asafe;
        const float arg   = (-1.0f / Asafe) * expf(fminf(boa, 80.0f));
        const bool  lam_ok = Apos && (arg >= MINW);

        // skip the Halley loop warp-uniformly while threshold unreachable
        if (__ballot_sync(0xffffffffu, lam_ok)) {
            float tc = 0.0f;
            bool valid = false;
            if (lam_ok) {
                // exact replica of the reference lambertw0 (f32, 12 Halley steps)
                float xw = fminf(fmaxf(arg, MINW), 0.0f);
                float wv = (xw < -0.25f)
                         ? (-1.0f + sqrtf(fmaxf(2.0f * (1.0f + EF * xw), 0.0f)))
                         : xw * (1.0f - xw);
                #pragma unroll
                for (int it = 0; it < 12; ++it) {
                    float ew = expf(wv);
                    float f  = wv * ew - xw;
                    float denom = ew * (wv + 1.0f)
                                - (wv + 2.0f) * f / (2.0f * (wv + 1.0f) + 1e-12f);
                    wv = wv - f / (denom + 1e-12f);
                }
                tc = boa - wv;
                const float nxt = ts[k + 1];       // k=NIN-1 reads sentinel KNS
                valid = (t < KNS) && (tc >= t) && (tc <= nxt);
            }
            const unsigned vm = __ballot_sync(0xffffffffu, valid);
            if (vm) {
                const int src = __ffs((int)vm) - 1;   // first (lowest-k) valid lane
                result = __shfl_sync(0xffffffffu, tc, src);
                done = true;
            }
        }
        carryA += totA;
        carryB += totB;
    }

    if (lane == 0) out[b * NOUT + o] = result;
}

// ---------------------------------------------------------------------------
extern "C" void kernel_launch(void* const* d_in, const int* in_sizes, int n_in,
                              void* d_out, int out_size) {
    const float* x      = (const float*)d_in[0];   // [32, 1024]
    const float* weight = (const float*)d_in[1];   // [512, 1034]
    const float* pulse  = (const float*)d_in[2];   // [10]
    float* out = (float*)d_out;                    // [32, 512]

    sort_kernel<<<NB, 1024>>>(x, pulse);

    // one warp per (b, o): 32*512 warps, 8 warps / block
    const int warps = NB * NOUT;
    solve_kernel<<<warps / 8, 256>>>(weight, out);
}